// round 13
// baseline (speedup 1.0000x reference)
#include <cuda_runtime.h>
#include <cuda_bf16.h>
#include <cstdint>

// ---------------------------------------------------------------------------
// ESN_2D: B=256, H=W=32, n=128, alpha^2=25, START_T=1
//  Phase A: wavefront-within-CTA persistent kernel: 63 anti-diagonals, up to
//           8 cells per barrier pair, parity-double-buffered smem state,
//           fused bf16 feature emission ([b][s][d]) + exact border rows
//  Phase B: pipelined mma.sync Gram with ldmatrix.x4.trans fragments
//  Phase C: out-of-smem blocked Cholesky + blocked substitutions
// ---------------------------------------------------------------------------

#define GSTRIDE 66564  // 258*258

__device__ float g_G[(size_t)256 * GSTRIDE];
// bf16 split features, sample-major: [b(256)][s(1024)][d(256)]
__device__ unsigned short g_Fhi[(size_t)256 * 1024 * 256];
__device__ unsigned short g_Flo[(size_t)256 * 1024 * 256];

// ---- packed f32x2 helpers ----
__device__ __forceinline__ unsigned long long splat2(float x) {
    unsigned long long r;
    asm("mov.b64 %0, {%1, %1};" : "=l"(r) : "f"(x));
    return r;
}
__device__ __forceinline__ void fma2(unsigned long long &c, unsigned long long a,
                                     unsigned long long b) {
    asm("fma.rn.f32x2 %0, %1, %2, %0;" : "+l"(c) : "l"(a), "l"(b));
}
__device__ __forceinline__ float2 unpk(unsigned long long v) {
    float2 f;
    asm("mov.b64 {%0, %1}, %2;" : "=f"(f.x), "=f"(f.y) : "l"(v));
    return f;
}

// ---- cp.async helpers ----
__device__ __forceinline__ uint32_t smem_u32(const void* p) {
    uint32_t a;
    asm("{ .reg .u64 t; cvta.to.shared.u64 t, %1; cvt.u32.u64 %0, t; }" : "=r"(a) : "l"(p));
    return a;
}
__device__ __forceinline__ void cpasync16(uint32_t dst, const void* src) {
    asm volatile("cp.async.cg.shared.global [%0], [%1], 16;" :: "r"(dst), "l"(src) : "memory");
}
__device__ __forceinline__ void cpasync_commit() {
    asm volatile("cp.async.commit_group;" ::: "memory");
}
__device__ __forceinline__ void cpasync_wait1() {
    asm volatile("cp.async.wait_group 1;" ::: "memory");
}
__device__ __forceinline__ void cpasync_wait0() {
    asm volatile("cp.async.wait_group 0;" ::: "memory");
}

// ---- bf16 mma.sync + ldmatrix ----
__device__ __forceinline__ void mma16816(float* d, const uint32_t* a, const uint32_t* b) {
    asm volatile(
        "mma.sync.aligned.m16n8k16.row.col.f32.bf16.bf16.f32 "
        "{%0,%1,%2,%3}, {%4,%5,%6,%7}, {%8,%9}, {%0,%1,%2,%3};"
        : "+f"(d[0]), "+f"(d[1]), "+f"(d[2]), "+f"(d[3])
        : "r"(a[0]), "r"(a[1]), "r"(a[2]), "r"(a[3]), "r"(b[0]), "r"(b[1]));
}
__device__ __forceinline__ void ldsm4t(uint32_t& r0, uint32_t& r1, uint32_t& r2,
                                       uint32_t& r3, uint32_t addr) {
    asm volatile("ldmatrix.sync.aligned.m8n8.x4.trans.shared.b16 {%0,%1,%2,%3}, [%4];"
                 : "=r"(r0), "=r"(r1), "=r"(r2), "=r"(r3) : "r"(addr));
}

// fast tanh: 1 - 2/(e^{2x}+1)
__device__ __forceinline__ float fast_tanh(float x) {
    float e = __expf(2.f * x);
    return 1.f - __fdividef(2.f, e + 1.f);
}

// ---------------------------------------------------------------------------
// Phase A: wavefront-within-CTA. 128 CTAs (2 batches each), 256 threads.
// FMA threads: ip=t&63 (i-pair), jg=t>>6 (j-group). Tail: gi=t>>7, ri=t&127.
// S[p][g][33][128]: row 0 = zero boundary, row h+1 = latest state of row h.
// Diagonal d reads parity d&1, writes d&1^1. red[4 jg][2 g][8 cell][128].
// ---------------------------------------------------------------------------
#define S_FLOATS (2 * 2 * 33 * 128)   // 16896
#define RED_OFF  S_FLOATS
#define ESN_SMEM ((S_FLOATS + 4 * 2 * 8 * 128) * 4)  // 167936 bytes... (16896+8192)*4

__global__ void __launch_bounds__(256) esn_persist(const float* __restrict__ img,
                                                   const float* __restrict__ win,
                                                   const float* __restrict__ W1,
                                                   const float* __restrict__ W2)
{
    extern __shared__ float es[];
    float* S = es;                 // [p][g][hs][128]
    float* red = es + RED_OFF;     // [jg][g][ci][128]

    int b0 = blockIdx.x * 2;
    int t = threadIdx.x;
    int ip = t & 63;
    int jg = t >> 6;

    unsigned long long w1r[32], w2r[32];
#pragma unroll
    for (int m = 0; m < 32; ++m) {
        int j = jg * 32 + m;
        w1r[m] = *(const unsigned long long*)&W1[j * 128 + ip * 2];
        w2r[m] = *(const unsigned long long*)&W2[j * 128 + ip * 2];
    }

    for (int idx = t; idx < S_FLOATS; idx += 256) S[idx] = 0.f;
    __syncthreads();

    int gi = t >> 7;
    int ri = t & 127;
    float winv = win[ri];
    const float* imgb = img + (b0 + gi) * 1024;
    size_t fbase = (size_t)(b0 + gi) * 1024 * 256;

    float sumL = 0.f, sumU = 0.f, sumUL = 0.f, sumUU = 0.f, su = 0.f;

    for (int dg = 0; dg < 63; ++dg) {
        int p = dg & 1;
        int hmin = dg > 31 ? dg - 31 : 0;
        int hmax = dg < 31 ? dg : 31;
        int ncell = hmax - hmin + 1;
        for (int c0 = 0; c0 < ncell; c0 += 8) {
            int nc = ncell - c0;
            if (nc > 8) nc = 8;
            // ---- FMA phase ----
            for (int ci = 0; ci < nc; ++ci) {
                int h = hmin + c0 + ci;
#pragma unroll
                for (int g = 0; g < 2; ++g) {
                    // left = row h (hs=h+1), up = row h-1 (hs=h); zero rows give
                    // correct boundary values for w==0 / h==0 automatically.
                    const float* lb = &S[((p * 2 + g) * 33 + h + 1) * 128 + jg * 32];
                    const float* ub = &S[((p * 2 + g) * 33 + h) * 128 + jg * 32];
                    unsigned long long a0 = 0ull, a1 = 0ull, b0a = 0ull, b1a = 0ull;
#pragma unroll
                    for (int m4 = 0; m4 < 4; ++m4) {
                        float4 lv0 = *(const float4*)&lb[m4 * 8];
                        float4 uv0 = *(const float4*)&ub[m4 * 8];
                        float4 lv1 = *(const float4*)&lb[m4 * 8 + 4];
                        float4 uv1 = *(const float4*)&ub[m4 * 8 + 4];
                        fma2(a0, splat2(lv0.x), w1r[m4 * 8 + 0]);
                        fma2(b0a, splat2(uv0.x), w2r[m4 * 8 + 0]);
                        fma2(a1, splat2(lv1.x), w1r[m4 * 8 + 4]);
                        fma2(b1a, splat2(uv1.x), w2r[m4 * 8 + 4]);
                        fma2(a0, splat2(lv0.y), w1r[m4 * 8 + 1]);
                        fma2(b0a, splat2(uv0.y), w2r[m4 * 8 + 1]);
                        fma2(a1, splat2(lv1.y), w1r[m4 * 8 + 5]);
                        fma2(b1a, splat2(uv1.y), w2r[m4 * 8 + 5]);
                        fma2(a0, splat2(lv0.z), w1r[m4 * 8 + 2]);
                        fma2(b0a, splat2(uv0.z), w2r[m4 * 8 + 2]);
                        fma2(a1, splat2(lv1.z), w1r[m4 * 8 + 6]);
                        fma2(b1a, splat2(uv1.z), w2r[m4 * 8 + 6]);
                        fma2(a0, splat2(lv0.w), w1r[m4 * 8 + 3]);
                        fma2(b0a, splat2(uv0.w), w2r[m4 * 8 + 3]);
                        fma2(a1, splat2(lv1.w), w1r[m4 * 8 + 7]);
                        fma2(b1a, splat2(uv1.w), w2r[m4 * 8 + 7]);
                    }
                    float2 va0 = unpk(a0), va1 = unpk(a1);
                    float2 vb0 = unpk(b0a), vb1 = unpk(b1a);
                    *(float2*)&red[((jg * 2 + g) * 8 + ci) * 128 + ip * 2] =
                        make_float2((va0.x + va1.x) + (vb0.x + vb1.x),
                                    (va0.y + va1.y) + (vb0.y + vb1.y));
                }
            }
            __syncthreads();
            // ---- tail phase: thread owns (gi, ri) across chunk cells ----
            for (int ci = 0; ci < nc; ++ci) {
                int h = hmin + c0 + ci;
                int w = dg - h;
                int cell = h * 32 + w;
                float s = (red[((0 * 2 + gi) * 8 + ci) * 128 + ri] +
                           red[((1 * 2 + gi) * 8 + ci) * 128 + ri]) +
                          (red[((2 * 2 + gi) * 8 + ci) * 128 + ri] +
                           red[((3 * 2 + gi) * 8 + ci) * 128 + ri]);
                float x = imgb[cell];
                float v = fast_tanh(fmaf(x, winv, s));
                S[(((p ^ 1) * 2 + gi) * 33 + h + 1) * 128 + ri] = v;
                unsigned short hs = __bfloat16_as_ushort(__float2bfloat16_rn(v));
                float hf = __uint_as_float(((uint32_t)hs) << 16);
                unsigned short ls = __bfloat16_as_ushort(__float2bfloat16_rn(v - hf));
                if (h >= 1 && w <= 30) {   // left feature d=ri at (h, w+1)
                    size_t o = fbase + (size_t)((h - 1) * 31 + w) * 256 + ri;
                    g_Fhi[o] = hs;
                    g_Flo[o] = ls;
                    float u = imgb[cell + 1];
                    sumL += v;
                    sumUL = fmaf(u, v, sumUL);
                }
                if (w >= 1 && h <= 30) {   // up feature d=128+ri at (h+1, w)
                    size_t o = fbase + (size_t)(h * 31 + (w - 1)) * 256 + 128 + ri;
                    g_Fhi[o] = hs;
                    g_Flo[o] = ls;
                    float u = imgb[cell + 32];
                    sumU += v;
                    sumUU = fmaf(u, v, sumUU);
                }
                if (ri == 0 && h >= 1 && w >= 1) su += x;
            }
            __syncthreads();
        }
    }

    size_t gb = (size_t)(b0 + gi) * GSTRIDE;
    g_G[gb + (size_t)256 * 258 + ri] = sumL;
    g_G[gb + (size_t)256 * 258 + 128 + ri] = sumU;
    g_G[gb + (size_t)257 * 258 + ri] = sumUL;
    g_G[gb + (size_t)257 * 258 + 128 + ri] = sumUU;
    if (ri == 0) {
        g_G[gb + (size_t)256 * 258 + 256] = 961.f;
        g_G[gb + (size_t)257 * 258 + 256] = su;
    }
}

// ---------------------------------------------------------------------------
// gram_mma: [s][d]-layout, ldmatrix.x4.trans, 2-stage cp.async pipeline.
// (R12 passing version, unchanged)
// ---------------------------------------------------------------------------
#define RSH 136
#define MATSH (32 * RSH)

__global__ void __launch_bounds__(256, 2) gram_mma()
{
    extern __shared__ unsigned short sh[];
    int tile = blockIdx.x;
    int b = blockIdx.y;
    int ti = (tile > 0) ? 1 : 0;
    int tj = (tile == 2) ? 1 : 0;
    bool diag = (ti == tj);

    int tid = threadIdx.x;
    int lane = tid & 31;
    int wq = tid >> 5;
    int warp_m = wq >> 2;
    int warp_n = wq & 3;
    int l4 = lane >> 2;
    int lm2 = (lane & 3) * 2;

    const unsigned short* srcHi = &g_Fhi[(size_t)b * 1024 * 256];
    const unsigned short* srcLo = &g_Flo[(size_t)b * 1024 * 256];
    int dA = ti * 128, dB = tj * 128;

    uint32_t base_u32 = smem_u32(sh);

    int lg = lane >> 3, L8 = lane & 7;
    int a_row = L8 + ((lg >> 1) << 3);
    int a_col = (lg & 1) << 3;
    int b_row = L8 + ((lg & 1) << 3);
    int b_col = (lg >> 1) << 3;

    float d[16][4];
#pragma unroll
    for (int q = 0; q < 16; ++q)
#pragma unroll
        for (int r = 0; r < 4; ++r) d[q][r] = 0.f;

    auto issue = [&](int c, int st) {
        int s0 = c * 32;
        uint32_t stb = base_u32 + (uint32_t)(st * 4 * MATSH * 2);
#pragma unroll
        for (int q = 0; q < 2; ++q) {
            int idx = tid + q * 256;
            int r = idx >> 4, cc = idx & 15;
            size_t srow = (size_t)(s0 + r) * 256;
            uint32_t drow = (uint32_t)(r * RSH * 2 + cc * 16);
            cpasync16(stb + drow, srcHi + srow + dA + cc * 8);
            cpasync16(stb + MATSH * 2 + drow, srcLo + srow + dA + cc * 8);
            if (!diag) {
                cpasync16(stb + 2 * MATSH * 2 + drow, srcHi + srow + dB + cc * 8);
                cpasync16(stb + 3 * MATSH * 2 + drow, srcLo + srow + dB + cc * 8);
            }
        }
        cpasync_commit();
    };

    issue(0, 0);
    for (int c = 0; c < 32; ++c) {
        int st = c & 1;
        if (c + 1 < 32) { issue(c + 1, st ^ 1); cpasync_wait1(); }
        else            { cpasync_wait0(); }
        __syncthreads();

        uint32_t stb = base_u32 + (uint32_t)(st * 4 * MATSH * 2);
        uint32_t mAhi = stb;
        uint32_t mAlo = stb + MATSH * 2;
        uint32_t mBhi = diag ? mAhi : stb + 2 * MATSH * 2;
        uint32_t mBlo = diag ? mAlo : stb + 3 * MATSH * 2;

#pragma unroll
        for (int ks = 0; ks < 2; ++ks) {
            int s0 = ks * 16;
            uint32_t aoff = (uint32_t)(((s0 + a_row) * RSH + a_col) * 2);
            uint32_t boff = (uint32_t)(((s0 + b_row) * RSH + b_col) * 2);

            uint32_t aH[4][4], aL[4][4], bH[4][2], bL[4][2];
#pragma unroll
            for (int mt = 0; mt < 4; ++mt) {
                uint32_t dcol = (uint32_t)((warp_m * 64 + mt * 16) * 2);
                ldsm4t(aH[mt][0], aH[mt][1], aH[mt][2], aH[mt][3], mAhi + aoff + dcol);
                ldsm4t(aL[mt][0], aL[mt][1], aL[mt][2], aL[mt][3], mAlo + aoff + dcol);
            }
#pragma unroll
            for (int pp = 0; pp < 2; ++pp) {
                uint32_t ecol = (uint32_t)((warp_n * 32 + pp * 16) * 2);
                ldsm4t(bH[2 * pp][0], bH[2 * pp][1], bH[2 * pp + 1][0], bH[2 * pp + 1][1],
                       mBhi + boff + ecol);
                ldsm4t(bL[2 * pp][0], bL[2 * pp][1], bL[2 * pp + 1][0], bL[2 * pp + 1][1],
                       mBlo + boff + ecol);
            }
#pragma unroll
            for (int mt = 0; mt < 4; ++mt)
#pragma unroll
                for (int nt = 0; nt < 4; ++nt) {
                    mma16816(d[mt * 4 + nt], aH[mt], bH[nt]);
                    mma16816(d[mt * 4 + nt], aL[mt], bH[nt]);
                    mma16816(d[mt * 4 + nt], aH[mt], bL[nt]);
                }
        }
        __syncthreads();
    }

    size_t gb = (size_t)b * GSTRIDE;
#pragma unroll
    for (int mt = 0; mt < 4; ++mt) {
#pragma unroll
        for (int nt = 0; nt < 4; ++nt) {
            int i0 = ti * 128 + warp_m * 64 + mt * 16 + l4;
            int j0 = tj * 128 + warp_n * 32 + nt * 8 + lm2;
            float* dst0 = &g_G[gb + (size_t)i0 * 258 + j0];
            float* dst1 = &g_G[gb + (size_t)(i0 + 8) * 258 + j0];
            *(float2*)dst0 = make_float2(d[mt * 4 + nt][0], d[mt * 4 + nt][1]);
            *(float2*)dst1 = make_float2(d[mt * 4 + nt][2], d[mt * 4 + nt][3]);
        }
    }
}

// ---------------------------------------------------------------------------
// Phase C: out-of-smem blocked Cholesky (unchanged)
// ---------------------------------------------------------------------------
#define TRI(i) ((i) * ((i) + 1) / 2)
#define PTS 264
#define BRS 260

__global__ void __launch_bounds__(256, 2) solve_kernel(float* __restrict__ out)
{
    extern __shared__ float sm[];
    float* pan = sm;
    float* Pt  = sm + 8484;
    float* y   = sm + 16932;
    int b = blockIdx.x;
    int tid = threadIdx.x;
    float* A = &g_G[(size_t)b * GSTRIDE];

    for (int j = tid; j < 257; j += 256) y[j] = A[(size_t)257 * 258 + j];

    for (int kb = 0; kb < 256; kb += 32) {
        int Rf = 257 - kb;
        for (int idx = tid; idx < Rf * 32; idx += 256) {
            int r = idx >> 5, c = idx & 31;
            float v = A[(size_t)(kb + r) * 258 + kb + c];
            if (r == c) v += 25.f;
            pan[(kb + r) * 33 + c] = v;
        }
        __syncthreads();
        if (tid < 32) {
            for (int c = 0; c < 32; ++c) {
                float dsq = pan[(kb + c) * 33 + c];
                __syncwarp();
                float dv = sqrtf(dsq);
                if (tid == c) pan[(kb + c) * 33 + c] = dv;
                float lr = 0.f;
                if (tid > c) {
                    lr = pan[(kb + tid) * 33 + c] / dv;
                    pan[(kb + tid) * 33 + c] = lr;
                }
                __syncwarp();
                if (tid > c)
                    for (int c2 = c + 1; c2 <= tid; ++c2)
                        pan[(kb + tid) * 33 + c2] -= lr * pan[(kb + c2) * 33 + c];
                __syncwarp();
            }
        }
        __syncthreads();
        int base = kb + 32;
        int R = 257 - base;
        if (tid < R) {
            int i = base + tid;
            float row[32];
#pragma unroll
            for (int m = 0; m < 32; ++m) row[m] = pan[i * 33 + m];
#pragma unroll
            for (int c = 0; c < 32; ++c) {
                float v = row[c];
#pragma unroll
                for (int m = 0; m < c; ++m) v -= row[m] * pan[(kb + c) * 33 + m];
                row[c] = v / pan[(kb + c) * 33 + c];
            }
#pragma unroll
            for (int m = 0; m < 32; ++m) {
                pan[i * 33 + m] = row[m];
                Pt[m * PTS + tid] = row[m];
            }
        }
        __syncthreads();
        for (int idx = tid; idx < Rf * 32; idx += 256) {
            int r = idx >> 5, c = idx & 31;
            A[(size_t)(kb + r) * 258 + kb + c] = pan[(kb + r) * 33 + c];
        }
        if (R > 0) {
            int Gg = (R + 3) >> 2;
            int nt = Gg * (Gg + 1) / 2;
            for (int tIdx = tid; tIdx < nt; tIdx += 256) {
                int gi = (int)((sqrtf(8.f * tIdx + 1.f) - 1.f) * 0.5f);
                while (TRI(gi + 1) <= tIdx) ++gi;
                while (TRI(gi) > tIdx) --gi;
                int gj = tIdx - TRI(gi);
                int i0 = base + gi * 4, j0 = base + gj * 4;
                unsigned long long acc[4][2];
#pragma unroll
                for (int q = 0; q < 4; ++q) { acc[q][0] = 0ull; acc[q][1] = 0ull; }
#pragma unroll 8
                for (int m = 0; m < 32; ++m) {
                    float4 av = *(const float4*)&Pt[m * PTS + gi * 4];
                    ulonglong2 bv = *(const ulonglong2*)&Pt[m * PTS + gj * 4];
                    unsigned long long s;
                    s = splat2(av.x); fma2(acc[0][0], s, bv.x); fma2(acc[0][1], s, bv.y);
                    s = splat2(av.y); fma2(acc[1][0], s, bv.x); fma2(acc[1][1], s, bv.y);
                    s = splat2(av.z); fma2(acc[2][0], s, bv.x); fma2(acc[2][1], s, bv.y);
                    s = splat2(av.w); fma2(acc[3][0], s, bv.x); fma2(acc[3][1], s, bv.y);
                }
                if (i0 + 3 <= 256 && j0 + 3 <= 256) {
#pragma unroll
                    for (int q = 0; q < 4; ++q) {
                        float* ap = &A[(size_t)(i0 + q) * 258 + j0];
                        float2 o0 = *(float2*)ap;
                        float2 o1 = *(float2*)(ap + 2);
                        float2 v0 = unpk(acc[q][0]);
                        float2 v1 = unpk(acc[q][1]);
                        o0.x -= v0.x; o0.y -= v0.y;
                        o1.x -= v1.x; o1.y -= v1.y;
                        *(float2*)ap = o0;
                        *(float2*)(ap + 2) = o1;
                    }
                } else {
#pragma unroll
                    for (int q = 0; q < 4; ++q) {
                        int i = i0 + q;
                        if (i > 256) continue;
                        float2 v0 = unpk(acc[q][0]);
                        float2 v1 = unpk(acc[q][1]);
                        float vv[4] = {v0.x, v0.y, v1.x, v1.y};
#pragma unroll
                        for (int p = 0; p < 4; ++p) {
                            int j = j0 + p;
                            if (j > 256) continue;
                            A[(size_t)i * 258 + j] -= vv[p];
                        }
                    }
                }
            }
        }
        __syncthreads();
    }
    if (tid == 0)
        A[(size_t)256 * 258 + 256] = sqrtf(A[(size_t)256 * 258 + 256] + 25.f);
    __syncthreads();

    for (int kb = 0; kb < 256; kb += 32) {
        int Rf = 257 - kb;
        for (int idx = tid; idx < Rf * 32; idx += 256) {
            int r = idx >> 5, c = idx & 31;
            pan[(kb + r) * 33 + c] = A[(size_t)(kb + r) * 258 + kb + c];
        }
        __syncthreads();
        if (tid < 32) {
            float acc = y[kb + tid];
#pragma unroll
            for (int m = 0; m < 32; ++m) {
                float dm = pan[(kb + m) * 33 + m];
                if (tid == m) acc /= dm;
                float ym = __shfl_sync(0xffffffffu, acc, m);
                if (tid > m) acc -= pan[(kb + tid) * 33 + m] * ym;
            }
            y[kb + tid] = acc;
        }
        __syncthreads();
        int R = 225 - kb;
        if (tid < R) {
            int i = kb + 32 + tid;
            float acc = y[i];
#pragma unroll
            for (int c = 0; c < 32; ++c) acc -= pan[i * 33 + c] * y[kb + c];
            y[i] = acc;
        }
        __syncthreads();
    }
    if (tid == 0) y[256] /= A[(size_t)256 * 258 + 256];
    __syncthreads();

    if (tid == 0) y[256] /= A[(size_t)256 * 258 + 256];
    __syncthreads();
    {
        float x256 = y[256];
        if (tid < 256) y[tid] -= A[(size_t)256 * 258 + tid] * x256;
        __syncthreads();
    }
    for (int kb = 224; kb >= 0; kb -= 32) {
        for (int idx = tid; idx < 32 * 256; idx += 256) {
            int c = idx >> 8, j = idx & 255;
            pan[c * BRS + j] = A[(size_t)(kb + c) * 258 + j];
        }
        __syncthreads();
        if (tid < 32) {
            float acc = y[kb + tid];
#pragma unroll
            for (int m = 31; m >= 0; --m) {
                float dm = pan[m * BRS + kb + m];
                if (tid == m) acc /= dm;
                float ym = __shfl_sync(0xffffffffu, acc, m);
                if (tid < m) acc -= pan[m * BRS + kb + tid] * ym;
            }
            y[kb + tid] = acc;
        }
        __syncthreads();
        if (tid < kb) {
            float acc = y[tid];
#pragma unroll
            for (int c = 0; c < 32; ++c) acc -= pan[c * BRS + tid] * y[kb + c];
            y[tid] = acc;
        }
        __syncthreads();
    }
    for (int j = tid; j < 257; j += 256) out[b * 257 + j] = y[j];
}

// ---------------------------------------------------------------------------
extern "C" void kernel_launch(void* const* d_in, const int* in_sizes, int n_in,
                              void* d_out, int out_size)
{
    (void)in_sizes; (void)n_in; (void)out_size;
    const float* img = (const float*)d_in[0];
    const float* win = (const float*)d_in[1];
    const float* W1  = (const float*)d_in[2];
    const float* W2  = (const float*)d_in[3];
    float* out = (float*)d_out;

    int esn_smem = ESN_SMEM;  // 100352 B... computed from S+red floats
    cudaFuncSetAttribute(esn_persist, cudaFuncAttributeMaxDynamicSharedMemorySize,
                         esn_smem);
    int solve_smem = 17192 * (int)sizeof(float);
    cudaFuncSetAttribute(solve_kernel, cudaFuncAttributeMaxDynamicSharedMemorySize,
                         solve_smem);
    int gram_smem = 2 * 4 * MATSH * 2;  // 69632 B
    cudaFuncSetAttribute(gram_mma, cudaFuncAttributeMaxDynamicSharedMemorySize, gram_smem);

    esn_persist<<<128, 256, esn_smem>>>(img, win, W1, W2);
    gram_mma<<<dim3(3, 256), 256, gram_smem>>>();
    solve_kernel<<<256, 256, solve_smem>>>(out);
}

// round 14
// speedup vs baseline: 1.0577x; 1.0577x over previous
#include <cuda_runtime.h>
#include <cuda_bf16.h>
#include <cstdint>

// ---------------------------------------------------------------------------
// ESN_2D: B=256, H=W=32, n=128, alpha^2=25, START_T=1
//  Phase A: persistent wavefront (R12 version), fused bf16 feature emission
//           in [b][s][d] layout + exact fp32 Gram border rows
//  Phase B: 3-stage pipelined mma.sync Gram with ldmatrix.x4.trans
//  Phase C: out-of-smem blocked Cholesky + blocked substitutions
// ---------------------------------------------------------------------------

#define GSTRIDE 66564  // 258*258

__device__ float g_G[(size_t)256 * GSTRIDE];
// bf16 split features, sample-major: [b(256)][s(1024)][d(256)]
__device__ unsigned short g_Fhi[(size_t)256 * 1024 * 256];
__device__ unsigned short g_Flo[(size_t)256 * 1024 * 256];

// ---- packed f32x2 helpers ----
__device__ __forceinline__ unsigned long long splat2(float x) {
    unsigned long long r;
    asm("mov.b64 %0, {%1, %1};" : "=l"(r) : "f"(x));
    return r;
}
__device__ __forceinline__ void fma2(unsigned long long &c, unsigned long long a,
                                     unsigned long long b) {
    asm("fma.rn.f32x2 %0, %1, %2, %0;" : "+l"(c) : "l"(a), "l"(b));
}
__device__ __forceinline__ float2 unpk(unsigned long long v) {
    float2 f;
    asm("mov.b64 {%0, %1}, %2;" : "=f"(f.x), "=f"(f.y) : "l"(v));
    return f;
}

// ---- cp.async helpers ----
__device__ __forceinline__ uint32_t smem_u32(const void* p) {
    uint32_t a;
    asm("{ .reg .u64 t; cvta.to.shared.u64 t, %1; cvt.u32.u64 %0, t; }" : "=r"(a) : "l"(p));
    return a;
}
__device__ __forceinline__ void cpasync16(uint32_t dst, const void* src) {
    asm volatile("cp.async.cg.shared.global [%0], [%1], 16;" :: "r"(dst), "l"(src) : "memory");
}
__device__ __forceinline__ void cpasync_commit() {
    asm volatile("cp.async.commit_group;" ::: "memory");
}
__device__ __forceinline__ void cpasync_wait2() {
    asm volatile("cp.async.wait_group 2;" ::: "memory");
}
__device__ __forceinline__ void cpasync_wait0() {
    asm volatile("cp.async.wait_group 0;" ::: "memory");
}

// ---- bf16 mma.sync + ldmatrix ----
__device__ __forceinline__ void mma16816(float* d, const uint32_t* a, const uint32_t* b) {
    asm volatile(
        "mma.sync.aligned.m16n8k16.row.col.f32.bf16.bf16.f32 "
        "{%0,%1,%2,%3}, {%4,%5,%6,%7}, {%8,%9}, {%0,%1,%2,%3};"
        : "+f"(d[0]), "+f"(d[1]), "+f"(d[2]), "+f"(d[3])
        : "r"(a[0]), "r"(a[1]), "r"(a[2]), "r"(a[3]), "r"(b[0]), "r"(b[1]));
}
__device__ __forceinline__ void ldsm4t(uint32_t& r0, uint32_t& r1, uint32_t& r2,
                                       uint32_t& r3, uint32_t addr) {
    asm volatile("ldmatrix.sync.aligned.m8n8.x4.trans.shared.b16 {%0,%1,%2,%3}, [%4];"
                 : "=r"(r0), "=r"(r1), "=r"(r2), "=r"(r3) : "r"(addr));
}

// fast tanh: 1 - 2/(e^{2x}+1)
__device__ __forceinline__ float fast_tanh(float x) {
    float e = __expf(2.f * x);
    return 1.f - __fdividef(2.f, e + 1.f);
}

// ---------------------------------------------------------------------------
// Phase A: persistent recurrence + fused feature emission (R12 version).
// 128 CTAs (2 batches each), 256 threads.
// ---------------------------------------------------------------------------
__global__ void __launch_bounds__(256) esn_persist(const float* __restrict__ img,
                                                   const float* __restrict__ win,
                                                   const float* __restrict__ W1,
                                                   const float* __restrict__ W2)
{
    int b0 = blockIdx.x * 2;
    int t = threadIdx.x;
    int ip = t & 63;
    int jg = t >> 6;

    unsigned long long w1r[32], w2r[32];
#pragma unroll
    for (int m = 0; m < 32; ++m) {
        int j = jg * 32 + m;
        w1r[m] = *(const unsigned long long*)&W1[j * 128 + ip * 2];
        w2r[m] = *(const unsigned long long*)&W2[j * 128 + ip * 2];
    }

    __shared__ float rowbuf[2][32][128];
    __shared__ float lbuf[2][128];
    __shared__ float red[4][2][128];

    for (int idx = t; idx < 2 * 32 * 128; idx += 256)
        ((float*)rowbuf)[idx] = 0.f;

    int rg = t >> 7;
    int ri = t & 127;
    float winv = win[ri];
    const float* imgb = img + (b0 + rg) * 1024;
    size_t fbase = (size_t)(b0 + rg) * 1024 * 256;

    float sumL = 0.f, sumU = 0.f, sumUL = 0.f, sumUU = 0.f, su = 0.f;

    for (int h = 0; h < 32; ++h) {
        lbuf[rg][ri] = 0.f;
        __syncthreads();
        for (int w = 0; w < 32; ++w) {
            int cell = h * 32 + w;
#pragma unroll
            for (int g = 0; g < 2; ++g) {
                unsigned long long accA = 0ull, accB = 0ull;
                const float* lb = &lbuf[g][jg * 32];
                const float* ub = &rowbuf[g][w][jg * 32];
#pragma unroll
                for (int m4 = 0; m4 < 8; ++m4) {
                    float4 lv = *(const float4*)&lb[m4 * 4];
                    float4 uv = *(const float4*)&ub[m4 * 4];
                    fma2(accA, splat2(lv.x), w1r[m4 * 4 + 0]);
                    fma2(accB, splat2(uv.x), w2r[m4 * 4 + 0]);
                    fma2(accA, splat2(lv.y), w1r[m4 * 4 + 1]);
                    fma2(accB, splat2(uv.y), w2r[m4 * 4 + 1]);
                    fma2(accA, splat2(lv.z), w1r[m4 * 4 + 2]);
                    fma2(accB, splat2(uv.z), w2r[m4 * 4 + 2]);
                    fma2(accA, splat2(lv.w), w1r[m4 * 4 + 3]);
                    fma2(accB, splat2(uv.w), w2r[m4 * 4 + 3]);
                }
                float2 a = unpk(accA), bb = unpk(accB);
                *(float2*)&red[jg][g][ip * 2] = make_float2(a.x + bb.x, a.y + bb.y);
            }
            __syncthreads();
            {
                float s = (red[0][rg][ri] + red[1][rg][ri]) +
                          (red[2][rg][ri] + red[3][rg][ri]);
                float x = imgb[cell];
                float v = fast_tanh(fmaf(x, winv, s));
                lbuf[rg][ri] = v;
                rowbuf[rg][w][ri] = v;
                unsigned short hs = __bfloat16_as_ushort(__float2bfloat16_rn(v));
                float hf = __uint_as_float(((uint32_t)hs) << 16);
                unsigned short ls = __bfloat16_as_ushort(__float2bfloat16_rn(v - hf));
                if (h >= 1 && w <= 30) {           // left feature d=ri at (h, w+1)
                    size_t o = fbase + (size_t)((h - 1) * 31 + w) * 256 + ri;
                    g_Fhi[o] = hs;
                    g_Flo[o] = ls;
                    float u = imgb[cell + 1];
                    sumL += v;
                    sumUL = fmaf(u, v, sumUL);
                }
                if (w >= 1 && h <= 30) {           // up feature d=128+ri at (h+1, w)
                    size_t o = fbase + (size_t)(h * 31 + (w - 1)) * 256 + 128 + ri;
                    g_Fhi[o] = hs;
                    g_Flo[o] = ls;
                    float u = imgb[cell + 32];
                    sumU += v;
                    sumUU = fmaf(u, v, sumUU);
                }
                if (ri == 0 && h >= 1 && w >= 1) su += x;
            }
            __syncthreads();
        }
    }

    size_t gb = (size_t)(b0 + rg) * GSTRIDE;
    g_G[gb + (size_t)256 * 258 + ri] = sumL;
    g_G[gb + (size_t)256 * 258 + 128 + ri] = sumU;
    g_G[gb + (size_t)257 * 258 + ri] = sumUL;
    g_G[gb + (size_t)257 * 258 + 128 + ri] = sumUU;
    if (ri == 0) {
        g_G[gb + (size_t)256 * 258 + 256] = 961.f;
        g_G[gb + (size_t)257 * 258 + 256] = su;
    }
}

// ---------------------------------------------------------------------------
// gram_mma: [s][d]-layout, ldmatrix.x4.trans, 3-stage cp.async pipeline.
// smem: 3 stages * 4 mats * 32 rows * RSH(136) shorts = 104448 B -> 2 CTAs/SM.
// ---------------------------------------------------------------------------
#define RSH 136
#define MATSH (32 * RSH)
#define NSTAGE 3

__global__ void __launch_bounds__(256, 2) gram_mma()
{
    extern __shared__ unsigned short sh[];
    int tile = blockIdx.x;
    int b = blockIdx.y;
    int ti = (tile > 0) ? 1 : 0;
    int tj = (tile == 2) ? 1 : 0;
    bool diag = (ti == tj);

    int tid = threadIdx.x;
    int lane = tid & 31;
    int wq = tid >> 5;
    int warp_m = wq >> 2;
    int warp_n = wq & 3;
    int l4 = lane >> 2;
    int lm2 = (lane & 3) * 2;

    const unsigned short* srcHi = &g_Fhi[(size_t)b * 1024 * 256];
    const unsigned short* srcLo = &g_Flo[(size_t)b * 1024 * 256];
    int dA = ti * 128, dB = tj * 128;

    uint32_t base_u32 = smem_u32(sh);

    int lg = lane >> 3, L8 = lane & 7;
    int a_row = L8 + ((lg >> 1) << 3);
    int a_col = (lg & 1) << 3;
    int b_row = L8 + ((lg & 1) << 3);
    int b_col = (lg >> 1) << 3;

    float d[16][4];
#pragma unroll
    for (int q = 0; q < 16; ++q)
#pragma unroll
        for (int r = 0; r < 4; ++r) d[q][r] = 0.f;

    auto issue = [&](int c, int st) {
        int s0 = c * 32;
        uint32_t stb = base_u32 + (uint32_t)(st * 4 * MATSH * 2);
#pragma unroll
        for (int q = 0; q < 2; ++q) {
            int idx = tid + q * 256;
            int r = idx >> 4, cc = idx & 15;
            size_t srow = (size_t)(s0 + r) * 256;
            uint32_t drow = (uint32_t)(r * RSH * 2 + cc * 16);
            cpasync16(stb + drow, srcHi + srow + dA + cc * 8);
            cpasync16(stb + MATSH * 2 + drow, srcLo + srow + dA + cc * 8);
            if (!diag) {
                cpasync16(stb + 2 * MATSH * 2 + drow, srcHi + srow + dB + cc * 8);
                cpasync16(stb + 3 * MATSH * 2 + drow, srcLo + srow + dB + cc * 8);
            }
        }
        cpasync_commit();
    };

    issue(0, 0);
    issue(1, 1);
    int st = 0;
    for (int c = 0; c < 32; ++c) {
        if (c + 2 < 32) { issue(c + 2, (st + 2) % NSTAGE); cpasync_wait2(); }
        else if (c + 1 < 32) { cpasync_wait2(); }  // ≤1 outstanding anyway
        else { cpasync_wait0(); }
        __syncthreads();

        uint32_t stb = base_u32 + (uint32_t)(st * 4 * MATSH * 2);
        uint32_t mAhi = stb;
        uint32_t mAlo = stb + MATSH * 2;
        uint32_t mBhi = diag ? mAhi : stb + 2 * MATSH * 2;
        uint32_t mBlo = diag ? mAlo : stb + 3 * MATSH * 2;

#pragma unroll
        for (int ks = 0; ks < 2; ++ks) {
            int s0 = ks * 16;
            uint32_t aoff = (uint32_t)(((s0 + a_row) * RSH + a_col) * 2);
            uint32_t boff = (uint32_t)(((s0 + b_row) * RSH + b_col) * 2);

            uint32_t aH[4][4], aL[4][4], bH[4][2], bL[4][2];
#pragma unroll
            for (int mt = 0; mt < 4; ++mt) {
                uint32_t dcol = (uint32_t)((warp_m * 64 + mt * 16) * 2);
                ldsm4t(aH[mt][0], aH[mt][1], aH[mt][2], aH[mt][3], mAhi + aoff + dcol);
                ldsm4t(aL[mt][0], aL[mt][1], aL[mt][2], aL[mt][3], mAlo + aoff + dcol);
            }
#pragma unroll
            for (int pp = 0; pp < 2; ++pp) {
                uint32_t ecol = (uint32_t)((warp_n * 32 + pp * 16) * 2);
                ldsm4t(bH[2 * pp][0], bH[2 * pp][1], bH[2 * pp + 1][0], bH[2 * pp + 1][1],
                       mBhi + boff + ecol);
                ldsm4t(bL[2 * pp][0], bL[2 * pp][1], bL[2 * pp + 1][0], bL[2 * pp + 1][1],
                       mBlo + boff + ecol);
            }
#pragma unroll
            for (int mt = 0; mt < 4; ++mt)
#pragma unroll
                for (int nt = 0; nt < 4; ++nt) {
                    mma16816(d[mt * 4 + nt], aH[mt], bH[nt]);
                    mma16816(d[mt * 4 + nt], aL[mt], bH[nt]);
                    mma16816(d[mt * 4 + nt], aH[mt], bL[nt]);
                }
        }
        __syncthreads();
        st = (st + 1) % NSTAGE;
    }

    size_t gb = (size_t)b * GSTRIDE;
#pragma unroll
    for (int mt = 0; mt < 4; ++mt) {
#pragma unroll
        for (int nt = 0; nt < 4; ++nt) {
            int i0 = ti * 128 + warp_m * 64 + mt * 16 + l4;
            int j0 = tj * 128 + warp_n * 32 + nt * 8 + lm2;
            float* dst0 = &g_G[gb + (size_t)i0 * 258 + j0];
            float* dst1 = &g_G[gb + (size_t)(i0 + 8) * 258 + j0];
            *(float2*)dst0 = make_float2(d[mt * 4 + nt][0], d[mt * 4 + nt][1]);
            *(float2*)dst1 = make_float2(d[mt * 4 + nt][2], d[mt * 4 + nt][3]);
        }
    }
}

// ---------------------------------------------------------------------------
// Phase C: out-of-smem blocked Cholesky (unchanged)
// ---------------------------------------------------------------------------
#define TRI(i) ((i) * ((i) + 1) / 2)
#define PTS 264
#define BRS 260

__global__ void __launch_bounds__(256, 2) solve_kernel(float* __restrict__ out)
{
    extern __shared__ float sm[];
    float* pan = sm;
    float* Pt  = sm + 8484;
    float* y   = sm + 16932;
    int b = blockIdx.x;
    int tid = threadIdx.x;
    float* A = &g_G[(size_t)b * GSTRIDE];

    for (int j = tid; j < 257; j += 256) y[j] = A[(size_t)257 * 258 + j];

    for (int kb = 0; kb < 256; kb += 32) {
        int Rf = 257 - kb;
        for (int idx = tid; idx < Rf * 32; idx += 256) {
            int r = idx >> 5, c = idx & 31;
            float v = A[(size_t)(kb + r) * 258 + kb + c];
            if (r == c) v += 25.f;
            pan[(kb + r) * 33 + c] = v;
        }
        __syncthreads();
        if (tid < 32) {
            for (int c = 0; c < 32; ++c) {
                float dsq = pan[(kb + c) * 33 + c];
                __syncwarp();
                float dv = sqrtf(dsq);
                if (tid == c) pan[(kb + c) * 33 + c] = dv;
                float lr = 0.f;
                if (tid > c) {
                    lr = pan[(kb + tid) * 33 + c] / dv;
                    pan[(kb + tid) * 33 + c] = lr;
                }
                __syncwarp();
                if (tid > c)
                    for (int c2 = c + 1; c2 <= tid; ++c2)
                        pan[(kb + tid) * 33 + c2] -= lr * pan[(kb + c2) * 33 + c];
                __syncwarp();
            }
        }
        __syncthreads();
        int base = kb + 32;
        int R = 257 - base;
        if (tid < R) {
            int i = base + tid;
            float row[32];
#pragma unroll
            for (int m = 0; m < 32; ++m) row[m] = pan[i * 33 + m];
#pragma unroll
            for (int c = 0; c < 32; ++c) {
                float v = row[c];
#pragma unroll
                for (int m = 0; m < c; ++m) v -= row[m] * pan[(kb + c) * 33 + m];
                row[c] = v / pan[(kb + c) * 33 + c];
            }
#pragma unroll
            for (int m = 0; m < 32; ++m) {
                pan[i * 33 + m] = row[m];
                Pt[m * PTS + tid] = row[m];
            }
        }
        __syncthreads();
        for (int idx = tid; idx < Rf * 32; idx += 256) {
            int r = idx >> 5, c = idx & 31;
            A[(size_t)(kb + r) * 258 + kb + c] = pan[(kb + r) * 33 + c];
        }
        if (R > 0) {
            int Gg = (R + 3) >> 2;
            int nt = Gg * (Gg + 1) / 2;
            for (int tIdx = tid; tIdx < nt; tIdx += 256) {
                int gi = (int)((sqrtf(8.f * tIdx + 1.f) - 1.f) * 0.5f);
                while (TRI(gi + 1) <= tIdx) ++gi;
                while (TRI(gi) > tIdx) --gi;
                int gj = tIdx - TRI(gi);
                int i0 = base + gi * 4, j0 = base + gj * 4;
                unsigned long long acc[4][2];
#pragma unroll
                for (int q = 0; q < 4; ++q) { acc[q][0] = 0ull; acc[q][1] = 0ull; }
#pragma unroll 8
                for (int m = 0; m < 32; ++m) {
                    float4 av = *(const float4*)&Pt[m * PTS + gi * 4];
                    ulonglong2 bv = *(const ulonglong2*)&Pt[m * PTS + gj * 4];
                    unsigned long long s;
                    s = splat2(av.x); fma2(acc[0][0], s, bv.x); fma2(acc[0][1], s, bv.y);
                    s = splat2(av.y); fma2(acc[1][0], s, bv.x); fma2(acc[1][1], s, bv.y);
                    s = splat2(av.z); fma2(acc[2][0], s, bv.x); fma2(acc[2][1], s, bv.y);
                    s = splat2(av.w); fma2(acc[3][0], s, bv.x); fma2(acc[3][1], s, bv.y);
                }
                if (i0 + 3 <= 256 && j0 + 3 <= 256) {
#pragma unroll
                    for (int q = 0; q < 4; ++q) {
                        float* ap = &A[(size_t)(i0 + q) * 258 + j0];
                        float2 o0 = *(float2*)ap;
                        float2 o1 = *(float2*)(ap + 2);
                        float2 v0 = unpk(acc[q][0]);
                        float2 v1 = unpk(acc[q][1]);
                        o0.x -= v0.x; o0.y -= v0.y;
                        o1.x -= v1.x; o1.y -= v1.y;
                        *(float2*)ap = o0;
                        *(float2*)(ap + 2) = o1;
                    }
                } else {
#pragma unroll
                    for (int q = 0; q < 4; ++q) {
                        int i = i0 + q;
                        if (i > 256) continue;
                        float2 v0 = unpk(acc[q][0]);
                        float2 v1 = unpk(acc[q][1]);
                        float vv[4] = {v0.x, v0.y, v1.x, v1.y};
#pragma unroll
                        for (int p = 0; p < 4; ++p) {
                            int j = j0 + p;
                            if (j > 256) continue;
                            A[(size_t)i * 258 + j] -= vv[p];
                        }
                    }
                }
            }
        }
        __syncthreads();
    }
    if (tid == 0)
        A[(size_t)256 * 258 + 256] = sqrtf(A[(size_t)256 * 258 + 256] + 25.f);
    __syncthreads();

    for (int kb = 0; kb < 256; kb += 32) {
        int Rf = 257 - kb;
        for (int idx = tid; idx < Rf * 32; idx += 256) {
            int r = idx >> 5, c = idx & 31;
            pan[(kb + r) * 33 + c] = A[(size_t)(kb + r) * 258 + kb + c];
        }
        __syncthreads();
        if (tid < 32) {
            float acc = y[kb + tid];
#pragma unroll
            for (int m = 0; m < 32; ++m) {
                float dm = pan[(kb + m) * 33 + m];
                if (tid == m) acc /= dm;
                float ym = __shfl_sync(0xffffffffu, acc, m);
                if (tid > m) acc -= pan[(kb + tid) * 33 + m] * ym;
            }
            y[kb + tid] = acc;
        }
        __syncthreads();
        int R = 225 - kb;
        if (tid < R) {
            int i = kb + 32 + tid;
            float acc = y[i];
#pragma unroll
            for (int c = 0; c < 32; ++c) acc -= pan[i * 33 + c] * y[kb + c];
            y[i] = acc;
        }
        __syncthreads();
    }
    if (tid == 0) y[256] /= A[(size_t)256 * 258 + 256];
    __syncthreads();

    if (tid == 0) y[256] /= A[(size_t)256 * 258 + 256];
    __syncthreads();
    {
        float x256 = y[256];
        if (tid < 256) y[tid] -= A[(size_t)256 * 258 + tid] * x256;
        __syncthreads();
    }
    for (int kb = 224; kb >= 0; kb -= 32) {
        for (int idx = tid; idx < 32 * 256; idx += 256) {
            int c = idx >> 8, j = idx & 255;
            pan[c * BRS + j] = A[(size_t)(kb + c) * 258 + j];
        }
        __syncthreads();
        if (tid < 32) {
            float acc = y[kb + tid];
#pragma unroll
            for (int m = 31; m >= 0; --m) {
                float dm = pan[m * BRS + kb + m];
                if (tid == m) acc /= dm;
                float ym = __shfl_sync(0xffffffffu, acc, m);
                if (tid < m) acc -= pan[m * BRS + kb + tid] * ym;
            }
            y[kb + tid] = acc;
        }
        __syncthreads();
        if (tid < kb) {
            float acc = y[tid];
#pragma unroll
            for (int c = 0; c < 32; ++c) acc -= pan[c * BRS + tid] * y[kb + c];
            y[tid] = acc;
        }
        __syncthreads();
    }
    for (int j = tid; j < 257; j += 256) out[b * 257 + j] = y[j];
}

// ---------------------------------------------------------------------------
extern "C" void kernel_launch(void* const* d_in, const int* in_sizes, int n_in,
                              void* d_out, int out_size)
{
    (void)in_sizes; (void)n_in; (void)out_size;
    const float* img = (const float*)d_in[0];
    const float* win = (const float*)d_in[1];
    const float* W1  = (const float*)d_in[2];
    const float* W2  = (const float*)d_in[3];
    float* out = (float*)d_out;

    int solve_smem = 17192 * (int)sizeof(float);
    cudaFuncSetAttribute(solve_kernel, cudaFuncAttributeMaxDynamicSharedMemorySize,
                         solve_smem);
    int gram_smem = NSTAGE * 4 * MATSH * 2;  // 104448 B
    cudaFuncSetAttribute(gram_mma, cudaFuncAttributeMaxDynamicSharedMemorySize, gram_smem);

    esn_persist<<<128, 256>>>(img, win, W1, W2);
    gram_mma<<<dim3(3, 256), 256, gram_smem>>>();
    solve_kernel<<<256, 256, solve_smem>>>(out);
}